// round 14
// baseline (speedup 1.0000x reference)
#include <cuda_runtime.h>
#include <cuda_fp16.h>
#include <math.h>
#include <stdint.h>

#define NCHUNK 256
#define LC 512
#define HID 256
#define MD 283
#define DEPTH 7
#define LTOT (NCHUNK * LC)

// ---- conv smem geometry (fp16, 32-ic chunks) ----
#define AP 20                 // A pitch in 4B words (64B row + 16B pad); 20%32=20 -> ldmatrix conflict-free
#define AROWS 384             // max window 128 + 2*128
#define ASZ (AROWS * AP)      // 7680 words per A buffer
#define BSZH 12288            // words per B buffer (6 s x 32 nt x 32 lane x 2)
#define CONV_SMEM (2 * (ASZ + BSZH) * 4)   // 159744 bytes

// ---- proj smem geometry (tf32 path) ----
#define P2 52
#define A2SZ (128 * P2)
#define BSZ 12288
#define PROJ_SMEM (2 * (A2SZ + BSZ) * 4)

// Activation ping-pong, half, layout [n][pos][ch]
__device__ __half g_act[2][(size_t)LTOT * HID];
// Final conv layer output for heads: fp32 [n][ch][pos]
__device__ float g_headsF[(size_t)NCHUNK * HID * LC];
// Tower weights packed as m16n8k16 fp16 B-fragments:
// [layer][c(8)][s(6)][ntile(32)][lane(32)][reg(2)]  s = tap*2 + sub(k16 half)
__device__ unsigned g_wH[DEPTH * 8 * BSZH];
// Proj weights, tf32 fragment layout: [kstep(36)][ntile(32)][lane(32)][reg(2)]
__device__ float g_wpF[36 * 2048];

// ---------------------------------------------------------------------------
// Weight prep
// ---------------------------------------------------------------------------
__global__ void prep_kernel(const float* __restrict__ tower_w,
                            const float* __restrict__ w_proj) {
    int i = blockIdx.x * blockDim.x + threadIdx.x;
    if (i < DEPTH * 8 * BSZH) {
        int local = i % BSZH;
        int blk = i / BSZH;
        int c = blk & 7;
        int layer = blk >> 3;
        int r = local & 1;
        int ln = (local >> 1) & 31;
        int nt = (local >> 6) & 31;
        int s = local >> 11;                // 0..5
        int tap = s >> 1, sub = s & 1;
        int ic = c * 32 + sub * 16 + 2 * (ln & 3) + 8 * r;
        int oc = nt * 8 + (ln >> 2);
        float w0 = tower_w[((layer * HID + oc) * HID + ic) * 3 + tap];
        float w1 = tower_w[((layer * HID + oc) * HID + ic + 1) * 3 + tap];
        __half2 h2 = __floats2half2_rn(w0, w1);
        g_wH[i] = *(unsigned*)&h2;
    }
    if (i < 36 * 2048) {
        int reg = i & 1;
        int ln = (i >> 1) & 31;
        int nt = (i >> 6) & 31;
        int ks = i >> 11;
        int h = nt * 8 + (ln >> 2);
        int m = ks * 8 + (ln & 3) + 4 * reg;
        float v = (m < MD) ? w_proj[h * MD + m] : 0.f;
        unsigned tv; asm("cvt.rna.tf32.f32 %0, %1;" : "=r"(tv) : "f"(v));
        g_wpF[i] = __uint_as_float(tv);
    }
}

// ---------------------------------------------------------------------------
// Projection via mma.sync tf32; epilogue writes half [n][pos][ch].
// ---------------------------------------------------------------------------
__global__ __launch_bounds__(512, 1)
void proj_kernel(const float* __restrict__ x) {
    extern __shared__ float sm[];
    float* Ab[2] = {sm, sm + A2SZ};
    float* Bb[2] = {sm + 2 * A2SZ, sm + 2 * A2SZ + BSZ};
    uint32_t sbase = (uint32_t)__cvta_generic_to_shared(sm);
    uint32_t sAa[2] = {sbase, sbase + A2SZ * 4};
    uint32_t sBa[2] = {sbase + 2 * A2SZ * 4, sbase + (2 * A2SZ + BSZ) * 4};

    int m0 = blockIdx.x * 128;
    int tid = threadIdx.x;
    int lane = tid & 31;
    int warp = tid >> 5;
    int wm = warp & 3;
    int wn = warp >> 2;
    int tig = lane & 3;
    int grp = lane >> 2;

    float acc[2][8][4];
#pragma unroll
    for (int i = 0; i < 2; i++)
#pragma unroll
        for (int j = 0; j < 8; j++)
#pragma unroll
            for (int c = 0; c < 4; c++) acc[i][j][c] = 0.f;

    auto stage = [&](int c) {
        int kc = c * 48;
#pragma unroll
        for (int r = 0; r < 12; r++) {
            int idx = r * 512 + tid;
            int pos = idx / 48;
            int k = idx - pos * 48;
            int gk = kc + k;
            int ok = (gk < MD) ? 4 : 0;
            const float* gs = x + (size_t)(m0 + pos) * MD + (ok ? gk : 0);
            asm volatile("cp.async.ca.shared.global [%0], [%1], 4, %2;"
                         :: "r"(sAa[c & 1] + (unsigned)(pos * P2 + k) * 4u),
                            "l"(__cvta_generic_to_global(gs)), "r"(ok));
        }
        const float* ws = g_wpF + (size_t)c * BSZ;
#pragma unroll
        for (int r = 0; r < 6; r++) {
            int idx = r * 512 + tid;
            asm volatile("cp.async.cg.shared.global [%0], [%1], 16, 16;"
                         :: "r"(sBa[c & 1] + (unsigned)idx * 16u),
                            "l"(__cvta_generic_to_global(ws + idx * 4)));
        }
        asm volatile("cp.async.commit_group;" ::: "memory");
    };

    stage(0);
    for (int c = 0; c < 6; c++) {
        if (c < 5) {
            stage(c + 1);
            asm volatile("cp.async.wait_group 1;" ::: "memory");
        } else {
            asm volatile("cp.async.wait_group 0;" ::: "memory");
        }
        __syncthreads();
        const float* Abuf = Ab[c & 1];
        const float* Bbuf = Bb[c & 1];
#pragma unroll
        for (int ks = 0; ks < 6; ks++) {
            unsigned a[2][4], b[8][2];
#pragma unroll
            for (int i = 0; i < 2; i++) {
                const float* ar = Abuf + (wm * 32 + i * 16 + grp) * P2 + ks * 8 + tig;
                a[i][0] = __float_as_uint(ar[0]);
                a[i][1] = __float_as_uint(ar[8 * P2]);
                a[i][2] = __float_as_uint(ar[4]);
                a[i][3] = __float_as_uint(ar[8 * P2 + 4]);
            }
#pragma unroll
            for (int j = 0; j < 8; j++) {
                uint2 bv = ((const uint2*)Bbuf)[(ks * 32 + wn * 8 + j) * 32 + lane];
                b[j][0] = bv.x; b[j][1] = bv.y;
            }
#pragma unroll
            for (int i = 0; i < 2; i++)
#pragma unroll
                for (int j = 0; j < 8; j++) {
                    asm volatile(
                        "mma.sync.aligned.m16n8k8.row.col.f32.tf32.tf32.f32 "
                        "{%0,%1,%2,%3}, {%4,%5,%6,%7}, {%8,%9}, {%0,%1,%2,%3};"
                        : "+f"(acc[i][j][0]), "+f"(acc[i][j][1]),
                          "+f"(acc[i][j][2]), "+f"(acc[i][j][3])
                        : "r"(a[i][0]), "r"(a[i][1]), "r"(a[i][2]), "r"(a[i][3]),
                          "r"(b[j][0]), "r"(b[j][1]));
                }
        }
        __syncthreads();
    }

    int n = m0 >> 9;
    __half* outp = g_act[0];
#pragma unroll
    for (int j = 0; j < 8; j++) {
        int h0 = wn * 64 + j * 8 + tig * 2;
#pragma unroll
        for (int i = 0; i < 2; i++) {
            int posb = (m0 & 511) + wm * 32 + i * 16 + grp;
            __half2 lo = __floats2half2_rn(acc[i][j][0], acc[i][j][1]);
            __half2 hi = __floats2half2_rn(acc[i][j][2], acc[i][j][3]);
            *(__half2*)(outp + (size_t)(n * LC + posb) * HID + h0) = lo;
            *(__half2*)(outp + (size_t)(n * LC + posb + 8) * HID + h0) = hi;
        }
    }
}

// ---------------------------------------------------------------------------
// Stage one conv K-chunk (32 ic): A = window [l0-d, l0+128+d) x 32 ic (64B
// rows, 4x16B cp.async, 16B-aligned), tap-shared. B = packed fragments.
// ---------------------------------------------------------------------------
__device__ __forceinline__ void stage_chunk(const __half* __restrict__ actIn,
                                            const unsigned* __restrict__ wsrc,
                                            int c, int l0, int d, int n,
                                            uint32_t sA, uint32_t sB, int tid) {
    int ic0 = c * 32;
    int rows = 128 + 2 * d;
    int total = rows * 4;
#pragma unroll
    for (int r = 0; r < 3; r++) {
        int idx = r * 512 + tid;
        if (idx < total) {
            int row = idx >> 2;
            int pc = idx & 3;
            int pos = l0 - d + row;
            int ok = ((unsigned)pos < (unsigned)LC) ? 16 : 0;
            const __half* gs = actIn + (size_t)(n * LC + (ok ? pos : 0)) * HID
                               + ic0 + pc * 8;
            asm volatile("cp.async.cg.shared.global [%0], [%1], 16, %2;"
                         :: "r"(sA + (unsigned)(row * AP + pc * 4) * 4u),
                            "l"(__cvta_generic_to_global(gs)), "r"(ok));
        }
    }
#pragma unroll
    for (int r = 0; r < 6; r++) {
        int idx = r * 512 + tid;
        asm volatile("cp.async.cg.shared.global [%0], [%1], 16, 16;"
                     :: "r"(sB + (unsigned)idx * 16u),
                        "l"(__cvta_generic_to_global(wsrc + idx * 4)));
    }
    asm volatile("cp.async.commit_group;" ::: "memory");
}

// ---------------------------------------------------------------------------
// Dilated conv layer via mma.sync m16n8k16 fp16 + ldmatrix.x4 A fragments.
// CTA 128 pos x 256 oc, 512 threads (4m x 4n warps, warp tile 32 x 64).
// K = 768 in 8 chunks (32 ic x 3 taps = 6 k16-steps each), double-buffered.
// ---------------------------------------------------------------------------
__global__ __launch_bounds__(512, 1)
void conv_kernel(int layer, int d, int src, int last,
                 const float* __restrict__ bias) {
    extern __shared__ unsigned smu[];
    const unsigned* Bbf[2] = {smu + 2 * ASZ, smu + 2 * ASZ + BSZH};
    uint32_t sbase = (uint32_t)__cvta_generic_to_shared(smu);
    uint32_t sAa[2] = {sbase, sbase + ASZ * 4};
    uint32_t sBa[2] = {sbase + 2 * ASZ * 4, sbase + (2 * ASZ + BSZH) * 4};

    const __half* actIn = g_act[src];
    __half* actOut = g_act[src ^ 1];
    int l0 = blockIdx.x * 128;
    int n = blockIdx.y;

    int tid = threadIdx.x;
    int lane = tid & 31;
    int warp = tid >> 5;
    int wm = warp & 3;
    int wn = warp >> 2;
    int tig = lane & 3;
    int grp = lane >> 2;
    // ldmatrix lane->row/word mapping (x4: m0 rows0-7/k0-7, m1 rows8-15/k0-7,
    // m2 rows0-7/k8-15, m3 rows8-15/k8-15)
    int lm_row = (lane & 7) + ((lane >> 3) & 1) * 8;
    int lm_kw = ((lane >> 4) & 1) * 4;

    float acc[2][8][4];
#pragma unroll
    for (int i = 0; i < 2; i++)
#pragma unroll
        for (int j = 0; j < 8; j++)
#pragma unroll
            for (int c = 0; c < 4; c++) acc[i][j][c] = 0.f;

    const unsigned* wbase = g_wH + (size_t)layer * 8 * BSZH;
    stage_chunk(actIn, wbase, 0, l0, d, n, sAa[0], sBa[0], tid);

    for (int c = 0; c < 8; c++) {
        if (c < 7) {
            stage_chunk(actIn, wbase + (size_t)(c + 1) * BSZH, c + 1, l0, d, n,
                        sAa[(c + 1) & 1], sBa[(c + 1) & 1], tid);
            asm volatile("cp.async.wait_group 1;" ::: "memory");
        } else {
            asm volatile("cp.async.wait_group 0;" ::: "memory");
        }
        __syncthreads();
        uint32_t sAcur = sAa[c & 1];
        const unsigned* Bbuf = Bbf[c & 1];
#pragma unroll
        for (int s = 0; s < 6; s++) {
            int tap = s >> 1, sub = s & 1;
            int rowb = wm * 32 + tap * d + lm_row;
            unsigned a[2][4], b[8][2];
#pragma unroll
            for (int i = 0; i < 2; i++) {
                uint32_t ad = sAcur +
                    (unsigned)((rowb + i * 16) * AP + sub * 8 + lm_kw) * 4u;
                asm volatile(
                    "ldmatrix.sync.aligned.m8n8.x4.shared.b16 {%0,%1,%2,%3}, [%4];"
                    : "=r"(a[i][0]), "=r"(a[i][1]), "=r"(a[i][2]), "=r"(a[i][3])
                    : "r"(ad));
            }
#pragma unroll
            for (int j = 0; j < 8; j++) {
                uint2 bv = ((const uint2*)Bbuf)[(s * 32 + wn * 8 + j) * 32 + lane];
                b[j][0] = bv.x; b[j][1] = bv.y;
            }
#pragma unroll
            for (int i = 0; i < 2; i++)
#pragma unroll
                for (int j = 0; j < 8; j++) {
                    asm volatile(
                        "mma.sync.aligned.m16n8k16.row.col.f32.f16.f16.f32 "
                        "{%0,%1,%2,%3}, {%4,%5,%6,%7}, {%8,%9}, {%0,%1,%2,%3};"
                        : "+f"(acc[i][j][0]), "+f"(acc[i][j][1]),
                          "+f"(acc[i][j][2]), "+f"(acc[i][j][3])
                        : "r"(a[i][0]), "r"(a[i][1]), "r"(a[i][2]), "r"(a[i][3]),
                          "r"(b[j][0]), "r"(b[j][1]));
                }
        }
        __syncthreads();
    }

    // Epilogue: bias + gelu(c)+c
#pragma unroll
    for (int j = 0; j < 8; j++) {
        int oc0 = wn * 64 + j * 8 + tig * 2;
        float b0 = bias[oc0], b1 = bias[oc0 + 1];
#pragma unroll
        for (int i = 0; i < 2; i++) {
            int posb = l0 + wm * 32 + i * 16 + grp;
            float v[4];
#pragma unroll
            for (int cr = 0; cr < 4; cr++) {
                float cc = acc[i][j][cr] + ((cr & 1) ? b1 : b0);
                v[cr] = 0.5f * cc * (1.f + erff(cc * 0.70710678118654752f)) + cc;
            }
            if (last) {
                g_headsF[((size_t)n * HID + oc0) * LC + posb] = v[0];
                g_headsF[((size_t)n * HID + oc0 + 1) * LC + posb] = v[1];
                g_headsF[((size_t)n * HID + oc0) * LC + posb + 8] = v[2];
                g_headsF[((size_t)n * HID + oc0 + 1) * LC + posb + 8] = v[3];
            } else {
                *(__half2*)(actOut + (size_t)(n * LC + posb) * HID + oc0) =
                    __floats2half2_rn(v[0], v[1]);
                *(__half2*)(actOut + (size_t)(n * LC + posb + 8) * HID + oc0) =
                    __floats2half2_rn(v[2], v[3]);
            }
        }
    }
}

// ---------------------------------------------------------------------------
// Heads: profile conv (K=20, pad 9/10) + mean-pool + atpm + mask.
// ---------------------------------------------------------------------------
__global__ __launch_bounds__(256)
void heads_kernel(const float* __restrict__ w_prof, const float* __restrict__ b_prof,
                  const float* __restrict__ w_atpm, const float* __restrict__ b_atpm,
                  const int* __restrict__ npq, float* __restrict__ out) {
    const float* in = g_headsF;
    int n = blockIdx.x;
    int tid = threadIdx.x;

    __shared__ float wp[HID * 20];
    __shared__ float wa[HID];
    __shared__ __align__(16) float rows[2][4][LC];
    __shared__ float partial[256];

    for (int i = tid; i < HID * 20; i += 256) wp[i] = w_prof[i];
    wa[tid] = w_atpm[tid];

    const float* base = in + (size_t)n * HID * LC;
    uint32_t rsh = (uint32_t)__cvta_generic_to_shared(&rows[0][0][0]);

    auto stage = [&](int g, int buf) {
#pragma unroll
        for (int r2 = 0; r2 < 2; r2++) {
            int idx = r2 * 256 + tid;
            int r = idx >> 7;
            int pc = idx & 127;
            const float* gs = base + (size_t)(g * 4 + r) * LC + pc * 4;
            asm volatile("cp.async.cg.shared.global [%0], [%1], 16, 16;"
                         :: "r"(rsh + (unsigned)(buf * 4 * LC + r * LC + pc * 4) * 4u),
                            "l"(__cvta_generic_to_global(gs)));
        }
        asm volatile("cp.async.commit_group;" ::: "memory");
    };

    float p0 = 0.f, p1 = 0.f, ap = 0.f;
    stage(0, 0);
    for (int g = 0; g < 64; g++) {
        if (g < 63) {
            stage(g + 1, (g + 1) & 1);
            asm volatile("cp.async.wait_group 1;" ::: "memory");
        } else {
            asm volatile("cp.async.wait_group 0;" ::: "memory");
        }
        __syncthreads();
        const float* rg = &rows[g & 1][0][0];
#pragma unroll
        for (int r = 0; r < 4; r++) {
            int ic = g * 4 + r;
            const float* row = rg + r * LC;
            const float* wpr = &wp[ic * 20];
            float wv = wa[ic];
#pragma unroll
            for (int k = 0; k < 20; k++) {
                float w = wpr[k];
                int pos = tid + k - 9;
                if (pos >= 0 && pos < LC) p0 = fmaf(row[pos], w, p0);
                int pos2 = tid + 256 + k - 9;
                if (pos2 < LC) p1 = fmaf(row[pos2], w, p1);
            }
            ap = fmaf(wv, row[tid] + row[tid + 256], ap);
        }
        __syncthreads();
    }

    float bp = b_prof[0];
    out[256 + (size_t)n * LC + tid] = p0 + bp;
    out[256 + (size_t)n * LC + tid + 256] = p1 + bp;

    partial[tid] = ap;
    __syncthreads();
    for (int s = 128; s > 0; s >>= 1) {
        if (tid < s) partial[tid] += partial[tid + s];
        __syncthreads();
    }
    if (tid == 0) {
        float atpm = partial[0] * (1.f / 512.f) + b_atpm[0];
        int b = n >> 7, p = n & 127;
        int np;
        int q0 = npq[0], q1 = npq[1];
        if (q1 == 0) {
            int q2 = npq[2], q3 = npq[3];
            if (q3 == 0 && q2 >= 0 && q2 < 128 && q0 >= 0 && q0 < 128)
                np = (b == 0) ? q0 : q2;   // little-endian int64 [n0, n1]
            else
                np = (b == 0) ? q0 : q1;
        } else np = (b == 0) ? q0 : q1;
        out[n] = (p < np) ? atpm : 0.f;
    }
}

// ---------------------------------------------------------------------------
extern "C" void kernel_launch(void* const* d_in, const int* in_sizes, int n_in,
                              void* d_out, int out_size) {
    const float* x       = (const float*)d_in[0];
    const float* w_proj  = (const float*)d_in[1];
    const float* tower_w = (const float*)d_in[2];
    const float* tower_b = (const float*)d_in[3];
    const float* w_prof  = (const float*)d_in[4];
    const float* b_prof  = (const float*)d_in[5];
    const float* w_atpm  = (const float*)d_in[6];
    const float* b_atpm  = (const float*)d_in[7];
    const int*   n_peaks = (const int*)d_in[8];
    float* out = (float*)d_out;

    cudaFuncSetAttribute(conv_kernel,
                         cudaFuncAttributeMaxDynamicSharedMemorySize, CONV_SMEM);
    cudaFuncSetAttribute(proj_kernel,
                         cudaFuncAttributeMaxDynamicSharedMemorySize, PROJ_SMEM);

    prep_kernel<<<(DEPTH * 8 * BSZH + 255) / 256, 256>>>(tower_w, w_proj);
    proj_kernel<<<LTOT / 128, 512, PROJ_SMEM>>>(x);
    for (int i = 0; i < DEPTH; i++)
        conv_kernel<<<dim3(LC / 128, NCHUNK), 512, CONV_SMEM>>>(
            i, 2 << i, i & 1, i == DEPTH - 1, tower_b + i * HID);
    heads_kernel<<<NCHUNK, 256>>>(w_prof, b_prof, w_atpm, b_atpm, n_peaks, out);
}

// round 15
// speedup vs baseline: 1.3555x; 1.3555x over previous
#include <cuda_runtime.h>
#include <cuda_fp16.h>
#include <math.h>
#include <stdint.h>

#define NCHUNK 256
#define LC 512
#define HID 256
#define MD 283
#define DEPTH 7
#define LTOT (NCHUNK * LC)

// ---- conv smem geometry (fp16, 16-ic chunks, 4-deep pipeline) ----
#define AP 12                 // A pitch in words: 32B row + 16B pad; (12*grp+tig)%32 all-distinct
#define AROWS 384             // max window 128 + 2*128
#define ASZ (AROWS * AP)      // 4608 words per A buffer
#define BSZH 6144             // words per B buffer (3 ks x 32 nt x 32 lane x 2)
#define NBUF 4
#define CONV_SMEM (NBUF * (ASZ + BSZH) * 4)   // 172032 bytes

// ---- proj smem geometry (tf32 path) ----
#define P2 52
#define A2SZ (128 * P2)
#define BSZ 12288
#define PROJ_SMEM (2 * (A2SZ + BSZ) * 4)

// Activation ping-pong, half, layout [n][pos][ch]
__device__ __half g_act[2][(size_t)LTOT * HID];
// Final conv layer output for heads: fp32 [n][ch][pos]
__device__ float g_headsF[(size_t)NCHUNK * HID * LC];
// Tower weights packed as m16n8k16 fp16 B-fragments:
// [layer][kc16(16)][ks(3)][ntile(32)][lane(32)][reg(2)] (b32 = half2)
__device__ unsigned g_wH[DEPTH * 16 * BSZH];
// Proj weights, tf32 fragment layout: [kstep(36)][ntile(32)][lane(32)][reg(2)]
__device__ float g_wpF[36 * 2048];

// ---------------------------------------------------------------------------
// Weight prep
// ---------------------------------------------------------------------------
__global__ void prep_kernel(const float* __restrict__ tower_w,
                            const float* __restrict__ w_proj) {
    int i = blockIdx.x * blockDim.x + threadIdx.x;
    if (i < DEPTH * 16 * BSZH) {
        int local = i % BSZH;
        int blk = i / BSZH;
        int kc16 = blk & 15;
        int layer = blk >> 4;
        int r = local & 1;
        int lane = (local >> 1) & 31;
        int nt = (local >> 6) & 31;
        int ks = local >> 11;               // tap 0..2
        int g = lane >> 2, t = lane & 3;
        int ic = kc16 * 16 + 2 * t + 8 * r;
        int oc = nt * 8 + g;
        float w0 = tower_w[((layer * HID + oc) * HID + ic) * 3 + ks];
        float w1 = tower_w[((layer * HID + oc) * HID + ic + 1) * 3 + ks];
        __half2 h2 = __floats2half2_rn(w0, w1);
        g_wH[i] = *(unsigned*)&h2;
    }
    if (i < 36 * 2048) {
        int reg = i & 1;
        int ln = (i >> 1) & 31;
        int nt = (i >> 6) & 31;
        int ks = i >> 11;
        int h = nt * 8 + (ln >> 2);
        int m = ks * 8 + (ln & 3) + 4 * reg;
        float v = (m < MD) ? w_proj[h * MD + m] : 0.f;
        unsigned tv; asm("cvt.rna.tf32.f32 %0, %1;" : "=r"(tv) : "f"(v));
        g_wpF[i] = __uint_as_float(tv);
    }
}

// ---------------------------------------------------------------------------
// Projection via mma.sync tf32; epilogue writes half [n][pos][ch].
// ---------------------------------------------------------------------------
__global__ __launch_bounds__(512, 1)
void proj_kernel(const float* __restrict__ x) {
    extern __shared__ float sm[];
    float* Ab[2] = {sm, sm + A2SZ};
    float* Bb[2] = {sm + 2 * A2SZ, sm + 2 * A2SZ + BSZ};
    uint32_t sbase = (uint32_t)__cvta_generic_to_shared(sm);
    uint32_t sAa[2] = {sbase, sbase + A2SZ * 4};
    uint32_t sBa[2] = {sbase + 2 * A2SZ * 4, sbase + (2 * A2SZ + BSZ) * 4};

    int m0 = blockIdx.x * 128;
    int tid = threadIdx.x;
    int lane = tid & 31;
    int warp = tid >> 5;
    int wm = warp & 3;
    int wn = warp >> 2;
    int tig = lane & 3;
    int grp = lane >> 2;

    float acc[2][8][4];
#pragma unroll
    for (int i = 0; i < 2; i++)
#pragma unroll
        for (int j = 0; j < 8; j++)
#pragma unroll
            for (int c = 0; c < 4; c++) acc[i][j][c] = 0.f;

    auto stage = [&](int c) {
        int kc = c * 48;
#pragma unroll
        for (int r = 0; r < 12; r++) {
            int idx = r * 512 + tid;
            int pos = idx / 48;
            int k = idx - pos * 48;
            int gk = kc + k;
            int ok = (gk < MD) ? 4 : 0;
            const float* gs = x + (size_t)(m0 + pos) * MD + (ok ? gk : 0);
            asm volatile("cp.async.ca.shared.global [%0], [%1], 4, %2;"
                         :: "r"(sAa[c & 1] + (unsigned)(pos * P2 + k) * 4u),
                            "l"(__cvta_generic_to_global(gs)), "r"(ok));
        }
        const float* ws = g_wpF + (size_t)c * BSZ;
#pragma unroll
        for (int r = 0; r < 6; r++) {
            int idx = r * 512 + tid;
            asm volatile("cp.async.cg.shared.global [%0], [%1], 16, 16;"
                         :: "r"(sBa[c & 1] + (unsigned)idx * 16u),
                            "l"(__cvta_generic_to_global(ws + idx * 4)));
        }
        asm volatile("cp.async.commit_group;" ::: "memory");
    };

    stage(0);
    for (int c = 0; c < 6; c++) {
        if (c < 5) {
            stage(c + 1);
            asm volatile("cp.async.wait_group 1;" ::: "memory");
        } else {
            asm volatile("cp.async.wait_group 0;" ::: "memory");
        }
        __syncthreads();
        const float* Abuf = Ab[c & 1];
        const float* Bbuf = Bb[c & 1];
#pragma unroll
        for (int ks = 0; ks < 6; ks++) {
            unsigned a[2][4], b[8][2];
#pragma unroll
            for (int i = 0; i < 2; i++) {
                const float* ar = Abuf + (wm * 32 + i * 16 + grp) * P2 + ks * 8 + tig;
                a[i][0] = __float_as_uint(ar[0]);
                a[i][1] = __float_as_uint(ar[8 * P2]);
                a[i][2] = __float_as_uint(ar[4]);
                a[i][3] = __float_as_uint(ar[8 * P2 + 4]);
            }
#pragma unroll
            for (int j = 0; j < 8; j++) {
                uint2 bv = ((const uint2*)Bbuf)[(ks * 32 + wn * 8 + j) * 32 + lane];
                b[j][0] = bv.x; b[j][1] = bv.y;
            }
#pragma unroll
            for (int i = 0; i < 2; i++)
#pragma unroll
                for (int j = 0; j < 8; j++) {
                    asm volatile(
                        "mma.sync.aligned.m16n8k8.row.col.f32.tf32.tf32.f32 "
                        "{%0,%1,%2,%3}, {%4,%5,%6,%7}, {%8,%9}, {%0,%1,%2,%3};"
                        : "+f"(acc[i][j][0]), "+f"(acc[i][j][1]),
                          "+f"(acc[i][j][2]), "+f"(acc[i][j][3])
                        : "r"(a[i][0]), "r"(a[i][1]), "r"(a[i][2]), "r"(a[i][3]),
                          "r"(b[j][0]), "r"(b[j][1]));
                }
        }
        __syncthreads();
    }

    int n = m0 >> 9;
    __half* outp = g_act[0];
#pragma unroll
    for (int j = 0; j < 8; j++) {
        int h0 = wn * 64 + j * 8 + tig * 2;
#pragma unroll
        for (int i = 0; i < 2; i++) {
            int posb = (m0 & 511) + wm * 32 + i * 16 + grp;
            __half2 lo = __floats2half2_rn(acc[i][j][0], acc[i][j][1]);
            __half2 hi = __floats2half2_rn(acc[i][j][2], acc[i][j][3]);
            *(__half2*)(outp + (size_t)(n * LC + posb) * HID + h0) = lo;
            *(__half2*)(outp + (size_t)(n * LC + posb + 8) * HID + h0) = hi;
        }
    }
}

// ---------------------------------------------------------------------------
// Stage one conv K-chunk (16 ic): A = window [l0-d, l0+128+d) rows of 32B
// (4 x 8B cp.async), tap-shared. B = packed fragments. Empty c -> bare commit.
// ---------------------------------------------------------------------------
__device__ __forceinline__ void stage_chunk(const __half* __restrict__ actIn,
                                            const unsigned* __restrict__ wb,
                                            int c, int l0, int d, int n,
                                            uint32_t sA, uint32_t sB, int tid) {
    if (c < 16) {
        int ic0 = c * 16;
        int rows = 128 + 2 * d;
        int total = rows * 4;
#pragma unroll
        for (int r = 0; r < 3; r++) {
            int idx = r * 512 + tid;
            if (idx < total) {
                int row = idx >> 2;
                int pc = idx & 3;
                int pos = l0 - d + row;
                int ok = ((unsigned)pos < (unsigned)LC) ? 8 : 0;
                const __half* gs = actIn + (size_t)(n * LC + (ok ? pos : 0)) * HID
                                   + ic0 + pc * 4;
                asm volatile("cp.async.ca.shared.global [%0], [%1], 8, %2;"
                             :: "r"(sA + (unsigned)(row * AP + pc * 2) * 4u),
                                "l"(__cvta_generic_to_global(gs)), "r"(ok));
            }
        }
        const unsigned* wsrc = wb + (size_t)c * BSZH;
#pragma unroll
        for (int r = 0; r < 3; r++) {
            int idx = r * 512 + tid;
            asm volatile("cp.async.cg.shared.global [%0], [%1], 16, 16;"
                         :: "r"(sB + (unsigned)idx * 16u),
                            "l"(__cvta_generic_to_global(wsrc + idx * 4)));
        }
    }
    asm volatile("cp.async.commit_group;" ::: "memory");
}

// ---------------------------------------------------------------------------
// Dilated conv layer via mma.sync m16n8k16 fp16, scalar-LDS fragments.
// CTA 128 pos x 256 oc, 512 threads (4m x 4n warps, warp tile 32 x 64).
// K = 768 in 16 chunks; 4-deep cp.async pipeline, ONE barrier per chunk.
// ---------------------------------------------------------------------------
__global__ __launch_bounds__(512, 1)
void conv_kernel(int layer, int d, int src, int last,
                 const float* __restrict__ bias) {
    extern __shared__ unsigned smu[];
    uint32_t sbase = (uint32_t)__cvta_generic_to_shared(smu);
    const unsigned* Abf[NBUF];
    const unsigned* Bbf[NBUF];
    uint32_t sAa[NBUF], sBa[NBUF];
#pragma unroll
    for (int b = 0; b < NBUF; b++) {
        Abf[b] = smu + b * (ASZ + BSZH);
        Bbf[b] = smu + b * (ASZ + BSZH) + ASZ;
        sAa[b] = sbase + (unsigned)(b * (ASZ + BSZH)) * 4u;
        sBa[b] = sbase + (unsigned)(b * (ASZ + BSZH) + ASZ) * 4u;
    }

    const __half* actIn = g_act[src];
    __half* actOut = g_act[src ^ 1];
    int l0 = blockIdx.x * 128;
    int n = blockIdx.y;

    int tid = threadIdx.x;
    int lane = tid & 31;
    int warp = tid >> 5;
    int wm = warp & 3;
    int wn = warp >> 2;
    int tig = lane & 3;
    int grp = lane >> 2;

    float acc[2][8][4];
#pragma unroll
    for (int i = 0; i < 2; i++)
#pragma unroll
        for (int j = 0; j < 8; j++)
#pragma unroll
            for (int c = 0; c < 4; c++) acc[i][j][c] = 0.f;

    const unsigned* wbase = g_wH + (size_t)layer * 16 * BSZH;
    stage_chunk(actIn, wbase, 0, l0, d, n, sAa[0], sBa[0], tid);
    stage_chunk(actIn, wbase, 1, l0, d, n, sAa[1], sBa[1], tid);

    for (int c = 0; c < 16; c++) {
        int nb = (c + 2) & (NBUF - 1);
        stage_chunk(actIn, wbase, c + 2, l0, d, n, sAa[nb], sBa[nb], tid);
        asm volatile("cp.async.wait_group 2;" ::: "memory");
        __syncthreads();
        const unsigned* Abuf = Abf[c & (NBUF - 1)];
        const unsigned* Bbuf = Bbf[c & (NBUF - 1)];
#pragma unroll
        for (int ks = 0; ks < 3; ks++) {
            int rowb = wm * 32 + ks * d + grp;   // buffer row = mpos + d + (ks-1)*d
            unsigned a[2][4], b[8][2];
#pragma unroll
            for (int i = 0; i < 2; i++) {
                int rb = rowb + i * 16;
                a[i][0] = Abuf[rb * AP + tig];
                a[i][1] = Abuf[(rb + 8) * AP + tig];
                a[i][2] = Abuf[rb * AP + tig + 4];
                a[i][3] = Abuf[(rb + 8) * AP + tig + 4];
            }
#pragma unroll
            for (int j = 0; j < 8; j++) {
                uint2 bv = ((const uint2*)Bbuf)[(ks * 32 + wn * 8 + j) * 32 + lane];
                b[j][0] = bv.x; b[j][1] = bv.y;
            }
#pragma unroll
            for (int i = 0; i < 2; i++)
#pragma unroll
                for (int j = 0; j < 8; j++) {
                    asm volatile(
                        "mma.sync.aligned.m16n8k16.row.col.f32.f16.f16.f32 "
                        "{%0,%1,%2,%3}, {%4,%5,%6,%7}, {%8,%9}, {%0,%1,%2,%3};"
                        : "+f"(acc[i][j][0]), "+f"(acc[i][j][1]),
                          "+f"(acc[i][j][2]), "+f"(acc[i][j][3])
                        : "r"(a[i][0]), "r"(a[i][1]), "r"(a[i][2]), "r"(a[i][3]),
                          "r"(b[j][0]), "r"(b[j][1]));
                }
        }
    }

    // Epilogue: bias + gelu(c)+c
#pragma unroll
    for (int j = 0; j < 8; j++) {
        int oc0 = wn * 64 + j * 8 + tig * 2;
        float b0 = bias[oc0], b1 = bias[oc0 + 1];
#pragma unroll
        for (int i = 0; i < 2; i++) {
            int posb = l0 + wm * 32 + i * 16 + grp;
            float v[4];
#pragma unroll
            for (int cr = 0; cr < 4; cr++) {
                float cc = acc[i][j][cr] + ((cr & 1) ? b1 : b0);
                v[cr] = 0.5f * cc * (1.f + erff(cc * 0.70710678118654752f)) + cc;
            }
            if (last) {
                g_headsF[((size_t)n * HID + oc0) * LC + posb] = v[0];
                g_headsF[((size_t)n * HID + oc0 + 1) * LC + posb] = v[1];
                g_headsF[((size_t)n * HID + oc0) * LC + posb + 8] = v[2];
                g_headsF[((size_t)n * HID + oc0 + 1) * LC + posb + 8] = v[3];
            } else {
                *(__half2*)(actOut + (size_t)(n * LC + posb) * HID + oc0) =
                    __floats2half2_rn(v[0], v[1]);
                *(__half2*)(actOut + (size_t)(n * LC + posb + 8) * HID + oc0) =
                    __floats2half2_rn(v[2], v[3]);
            }
        }
    }
}

// ---------------------------------------------------------------------------
// Heads: profile conv (K=20, pad 9/10) + mean-pool + atpm + mask.
// ---------------------------------------------------------------------------
__global__ __launch_bounds__(256)
void heads_kernel(const float* __restrict__ w_prof, const float* __restrict__ b_prof,
                  const float* __restrict__ w_atpm, const float* __restrict__ b_atpm,
                  const int* __restrict__ npq, float* __restrict__ out) {
    const float* in = g_headsF;
    int n = blockIdx.x;
    int tid = threadIdx.x;

    __shared__ float wp[HID * 20];
    __shared__ float wa[HID];
    __shared__ __align__(16) float rows[2][4][LC];
    __shared__ float partial[256];

    for (int i = tid; i < HID * 20; i += 256) wp[i] = w_prof[i];
    wa[tid] = w_atpm[tid];

    const float* base = in + (size_t)n * HID * LC;
    uint32_t rsh = (uint32_t)__cvta_generic_to_shared(&rows[0][0][0]);

    auto stage = [&](int g, int buf) {
#pragma unroll
        for (int r2 = 0; r2 < 2; r2++) {
            int idx = r2 * 256 + tid;
            int r = idx >> 7;
            int pc = idx & 127;
            const float* gs = base + (size_t)(g * 4 + r) * LC + pc * 4;
            asm volatile("cp.async.cg.shared.global [%0], [%1], 16, 16;"
                         :: "r"(rsh + (unsigned)(buf * 4 * LC + r * LC + pc * 4) * 4u),
                            "l"(__cvta_generic_to_global(gs)));
        }
        asm volatile("cp.async.commit_group;" ::: "memory");
    };

    float p0 = 0.f, p1 = 0.f, ap = 0.f;
    stage(0, 0);
    for (int g = 0; g < 64; g++) {
        if (g < 63) {
            stage(g + 1, (g + 1) & 1);
            asm volatile("cp.async.wait_group 1;" ::: "memory");
        } else {
            asm volatile("cp.async.wait_group 0;" ::: "memory");
        }
        __syncthreads();
        const float* rg = &rows[g & 1][0][0];
#pragma unroll
        for (int r = 0; r < 4; r++) {
            int ic = g * 4 + r;
            const float* row = rg + r * LC;
            const float* wpr = &wp[ic * 20];
            float wv = wa[ic];
#pragma unroll
            for (int k = 0; k < 20; k++) {
                float w = wpr[k];
                int pos = tid + k - 9;
                if (pos >= 0 && pos < LC) p0 = fmaf(row[pos], w, p0);
                int pos2 = tid + 256 + k - 9;
                if (pos2 < LC) p1 = fmaf(row[pos2], w, p1);
            }
            ap = fmaf(wv, row[tid] + row[tid + 256], ap);
        }
        __syncthreads();
    }

    float bp = b_prof[0];
    out[256 + (size_t)n * LC + tid] = p0 + bp;
    out[256 + (size_t)n * LC + tid + 256] = p1 + bp;

    partial[tid] = ap;
    __syncthreads();
    for (int s = 128; s > 0; s >>= 1) {
        if (tid < s) partial[tid] += partial[tid + s];
        __syncthreads();
    }
    if (tid == 0) {
        float atpm = partial[0] * (1.f / 512.f) + b_atpm[0];
        int b = n >> 7, p = n & 127;
        int np;
        int q0 = npq[0], q1 = npq[1];
        if (q1 == 0) {
            int q2 = npq[2], q3 = npq[3];
            if (q3 == 0 && q2 >= 0 && q2 < 128 && q0 >= 0 && q0 < 128)
                np = (b == 0) ? q0 : q2;   // little-endian int64 [n0, n1]
            else
                np = (b == 0) ? q0 : q1;
        } else np = (b == 0) ? q0 : q1;
        out[n] = (p < np) ? atpm : 0.f;
    }
}

// ---------------------------------------------------------------------------
extern "C" void kernel_launch(void* const* d_in, const int* in_sizes, int n_in,
                              void* d_out, int out_size) {
    const float* x       = (const float*)d_in[0];
    const float* w_proj  = (const float*)d_in[1];
    const float* tower_w = (const float*)d_in[2];
    const float* tower_b = (const float*)d_in[3];
    const float* w_prof  = (const float*)d_in[4];
    const float* b_prof  = (const float*)d_in[5];
    const float* w_atpm  = (const float*)d_in[6];
    const float* b_atpm  = (const float*)d_in[7];
    const int*   n_peaks = (const int*)d_in[8];
    float* out = (float*)d_out;

    cudaFuncSetAttribute(conv_kernel,
                         cudaFuncAttributeMaxDynamicSharedMemorySize, CONV_SMEM);
    cudaFuncSetAttribute(proj_kernel,
                         cudaFuncAttributeMaxDynamicSharedMemorySize, PROJ_SMEM);

    prep_kernel<<<(DEPTH * 16 * BSZH + 255) / 256, 256>>>(tower_w, w_proj);
    proj_kernel<<<LTOT / 128, 512, PROJ_SMEM>>>(x);
    for (int i = 0; i < DEPTH; i++)
        conv_kernel<<<dim3(LC / 128, NCHUNK), 512, CONV_SMEM>>>(
            i, 2 << i, i & 1, i == DEPTH - 1, tower_b + i * HID);
    heads_kernel<<<NCHUNK, 256>>>(w_prof, b_prof, w_atpm, b_atpm, n_peaks, out);
}

// round 16
// speedup vs baseline: 1.3718x; 1.0120x over previous
#include <cuda_runtime.h>
#include <cuda_fp16.h>
#include <math.h>
#include <stdint.h>

#define NCHUNK 256
#define LC 512
#define HID 256
#define MD 283
#define DEPTH 7
#define LTOT (NCHUNK * LC)

// ---- conv smem geometry (R13: fp16, 16-ic chunks, 2-buffer) ----
#define AP 36                 // A pitch in 4B words; (4*grp+tig)%32 all-distinct
#define AROWS 384             // max window 128 + 2*128
#define ASZ (AROWS * AP)      // 13824 words per A buffer
#define BSZH 6144             // words per B buffer (3 ks x 32 nt x 32 lane x 2)
#define CONV_SMEM (2 * (ASZ + BSZH) * 4)   // 159744 bytes

// ---- proj smem geometry (tf32 path) ----
#define P2 52
#define A2SZ (128 * P2)
#define BSZ 12288
#define PROJ_SMEM (2 * (A2SZ + BSZ) * 4)

// Activation ping-pong, half, layout [n][pos][ch]
__device__ __half g_act[2][(size_t)LTOT * HID];
// Final conv layer output for heads: fp32 [n][ch][pos]
__device__ float g_headsF[(size_t)NCHUNK * HID * LC];
// Tower weights packed as m16n8k16 fp16 B-fragments:
// [layer][kc16(16)][ks(3)][ntile(32)][lane(32)][reg(2)] (b32 = half2)
__device__ unsigned g_wH[DEPTH * 16 * BSZH];
// Proj weights, tf32 fragment layout: [kstep(36)][ntile(32)][lane(32)][reg(2)]
__device__ float g_wpF[36 * 2048];
// atpm partial sums: [n][half]
__device__ float g_atpmP[NCHUNK * 2];

// ---------------------------------------------------------------------------
// Weight prep
// ---------------------------------------------------------------------------
__global__ void prep_kernel(const float* __restrict__ tower_w,
                            const float* __restrict__ w_proj) {
    int i = blockIdx.x * blockDim.x + threadIdx.x;
    if (i < DEPTH * 16 * BSZH) {
        int local = i % BSZH;
        int blk = i / BSZH;
        int kc16 = blk & 15;
        int layer = blk >> 4;
        int r = local & 1;
        int lane = (local >> 1) & 31;
        int nt = (local >> 6) & 31;
        int ks = local >> 11;               // tap 0..2
        int g = lane >> 2, t = lane & 3;
        int ic = kc16 * 16 + 2 * t + 8 * r;
        int oc = nt * 8 + g;
        float w0 = tower_w[((layer * HID + oc) * HID + ic) * 3 + ks];
        float w1 = tower_w[((layer * HID + oc) * HID + ic + 1) * 3 + ks];
        __half2 h2 = __floats2half2_rn(w0, w1);
        g_wH[i] = *(unsigned*)&h2;
    }
    if (i < 36 * 2048) {
        int reg = i & 1;
        int ln = (i >> 1) & 31;
        int nt = (i >> 6) & 31;
        int ks = i >> 11;
        int h = nt * 8 + (ln >> 2);
        int m = ks * 8 + (ln & 3) + 4 * reg;
        float v = (m < MD) ? w_proj[h * MD + m] : 0.f;
        unsigned tv; asm("cvt.rna.tf32.f32 %0, %1;" : "=r"(tv) : "f"(v));
        g_wpF[i] = __uint_as_float(tv);
    }
}

// ---------------------------------------------------------------------------
// Projection via mma.sync tf32; epilogue writes half [n][pos][ch].
// ---------------------------------------------------------------------------
__global__ __launch_bounds__(512, 1)
void proj_kernel(const float* __restrict__ x) {
    extern __shared__ float sm[];
    float* Ab[2] = {sm, sm + A2SZ};
    float* Bb[2] = {sm + 2 * A2SZ, sm + 2 * A2SZ + BSZ};
    uint32_t sbase = (uint32_t)__cvta_generic_to_shared(sm);
    uint32_t sAa[2] = {sbase, sbase + A2SZ * 4};
    uint32_t sBa[2] = {sbase + 2 * A2SZ * 4, sbase + (2 * A2SZ + BSZ) * 4};

    int m0 = blockIdx.x * 128;
    int tid = threadIdx.x;
    int lane = tid & 31;
    int warp = tid >> 5;
    int wm = warp & 3;
    int wn = warp >> 2;
    int tig = lane & 3;
    int grp = lane >> 2;

    float acc[2][8][4];
#pragma unroll
    for (int i = 0; i < 2; i++)
#pragma unroll
        for (int j = 0; j < 8; j++)
#pragma unroll
            for (int c = 0; c < 4; c++) acc[i][j][c] = 0.f;

    auto stage = [&](int c) {
        int kc = c * 48;
#pragma unroll
        for (int r = 0; r < 12; r++) {
            int idx = r * 512 + tid;
            int pos = idx / 48;
            int k = idx - pos * 48;
            int gk = kc + k;
            int ok = (gk < MD) ? 4 : 0;
            const float* gs = x + (size_t)(m0 + pos) * MD + (ok ? gk : 0);
            asm volatile("cp.async.ca.shared.global [%0], [%1], 4, %2;"
                         :: "r"(sAa[c & 1] + (unsigned)(pos * P2 + k) * 4u),
                            "l"(__cvta_generic_to_global(gs)), "r"(ok));
        }
        const float* ws = g_wpF + (size_t)c * BSZ;
#pragma unroll
        for (int r = 0; r < 6; r++) {
            int idx = r * 512 + tid;
            asm volatile("cp.async.cg.shared.global [%0], [%1], 16, 16;"
                         :: "r"(sBa[c & 1] + (unsigned)idx * 16u),
                            "l"(__cvta_generic_to_global(ws + idx * 4)));
        }
        asm volatile("cp.async.commit_group;" ::: "memory");
    };

    stage(0);
    for (int c = 0; c < 6; c++) {
        if (c < 5) {
            stage(c + 1);
            asm volatile("cp.async.wait_group 1;" ::: "memory");
        } else {
            asm volatile("cp.async.wait_group 0;" ::: "memory");
        }
        __syncthreads();
        const float* Abuf = Ab[c & 1];
        const float* Bbuf = Bb[c & 1];
#pragma unroll
        for (int ks = 0; ks < 6; ks++) {
            unsigned a[2][4], b[8][2];
#pragma unroll
            for (int i = 0; i < 2; i++) {
                const float* ar = Abuf + (wm * 32 + i * 16 + grp) * P2 + ks * 8 + tig;
                a[i][0] = __float_as_uint(ar[0]);
                a[i][1] = __float_as_uint(ar[8 * P2]);
                a[i][2] = __float_as_uint(ar[4]);
                a[i][3] = __float_as_uint(ar[8 * P2 + 4]);
            }
#pragma unroll
            for (int j = 0; j < 8; j++) {
                uint2 bv = ((const uint2*)Bbuf)[(ks * 32 + wn * 8 + j) * 32 + lane];
                b[j][0] = bv.x; b[j][1] = bv.y;
            }
#pragma unroll
            for (int i = 0; i < 2; i++)
#pragma unroll
                for (int j = 0; j < 8; j++) {
                    asm volatile(
                        "mma.sync.aligned.m16n8k8.row.col.f32.tf32.tf32.f32 "
                        "{%0,%1,%2,%3}, {%4,%5,%6,%7}, {%8,%9}, {%0,%1,%2,%3};"
                        : "+f"(acc[i][j][0]), "+f"(acc[i][j][1]),
                          "+f"(acc[i][j][2]), "+f"(acc[i][j][3])
                        : "r"(a[i][0]), "r"(a[i][1]), "r"(a[i][2]), "r"(a[i][3]),
                          "r"(b[j][0]), "r"(b[j][1]));
                }
        }
        __syncthreads();
    }

    int n = m0 >> 9;
    __half* outp = g_act[0];
#pragma unroll
    for (int j = 0; j < 8; j++) {
        int h0 = wn * 64 + j * 8 + tig * 2;
#pragma unroll
        for (int i = 0; i < 2; i++) {
            int posb = (m0 & 511) + wm * 32 + i * 16 + grp;
            __half2 lo = __floats2half2_rn(acc[i][j][0], acc[i][j][1]);
            __half2 hi = __floats2half2_rn(acc[i][j][2], acc[i][j][3]);
            *(__half2*)(outp + (size_t)(n * LC + posb) * HID + h0) = lo;
            *(__half2*)(outp + (size_t)(n * LC + posb + 8) * HID + h0) = hi;
        }
    }
}

// ---------------------------------------------------------------------------
// Stage one conv K-chunk: A = window [l0-d, l0+128+d) x 16 ic (half,
// 4 x 8B cp.async per row), tap-shared. B = packed fragments.
// ---------------------------------------------------------------------------
__device__ __forceinline__ void stage_chunk(const __half* __restrict__ actIn,
                                            const unsigned* __restrict__ wsrc,
                                            int kc16, int l0, int d, int n,
                                            uint32_t sA, uint32_t sB, int tid) {
    int ic0 = kc16 * 16;
    int rows = 128 + 2 * d;
    int total = rows * 4;
#pragma unroll
    for (int r = 0; r < 4; r++) {
        int idx = r * 512 + tid;
        if (idx < total) {
            int row = idx >> 2;
            int pc = idx & 3;
            int pos = l0 - d + row;
            int ok = ((unsigned)pos < (unsigned)LC) ? 8 : 0;
            const __half* gs = actIn + (size_t)(n * LC + (ok ? pos : 0)) * HID
                               + ic0 + pc * 4;
            asm volatile("cp.async.ca.shared.global [%0], [%1], 8, %2;"
                         :: "r"(sA + (unsigned)(row * AP + pc * 2) * 4u),
                            "l"(__cvta_generic_to_global(gs)), "r"(ok));
        }
    }
#pragma unroll
    for (int r = 0; r < 3; r++) {
        int idx = r * 512 + tid;
        asm volatile("cp.async.cg.shared.global [%0], [%1], 16, 16;"
                     :: "r"(sB + (unsigned)idx * 16u),
                        "l"(__cvta_generic_to_global(wsrc + idx * 4)));
    }
    asm volatile("cp.async.commit_group;" ::: "memory");
}

// ---------------------------------------------------------------------------
// Dilated conv layer via mma.sync m16n8k16 fp16 (R13 structure).
// CTA 128 pos x 256 oc, 512 threads; K = 768 in 16 chunks, double-buffered.
// ---------------------------------------------------------------------------
__global__ __launch_bounds__(512, 1)
void conv_kernel(int layer, int d, int src, int last,
                 const float* __restrict__ bias) {
    extern __shared__ unsigned smu[];
    const unsigned* Abf[2] = {smu, smu + ASZ};
    const unsigned* Bbf[2] = {smu + 2 * ASZ, smu + 2 * ASZ + BSZH};
    uint32_t sbase = (uint32_t)__cvta_generic_to_shared(smu);
    uint32_t sAa[2] = {sbase, sbase + ASZ * 4};
    uint32_t sBa[2] = {sbase + 2 * ASZ * 4, sbase + (2 * ASZ + BSZH) * 4};

    const __half* actIn = g_act[src];
    __half* actOut = g_act[src ^ 1];
    int l0 = blockIdx.x * 128;
    int n = blockIdx.y;

    int tid = threadIdx.x;
    int lane = tid & 31;
    int warp = tid >> 5;
    int wm = warp & 3;
    int wn = warp >> 2;
    int tig = lane & 3;
    int grp = lane >> 2;

    float acc[2][8][4];
#pragma unroll
    for (int i = 0; i < 2; i++)
#pragma unroll
        for (int j = 0; j < 8; j++)
#pragma unroll
            for (int c = 0; c < 4; c++) acc[i][j][c] = 0.f;

    const unsigned* wbase = g_wH + (size_t)layer * 16 * BSZH;
    stage_chunk(actIn, wbase, 0, l0, d, n, sAa[0], sBa[0], tid);

    for (int c = 0; c < 16; c++) {
        if (c < 15) {
            stage_chunk(actIn, wbase + (size_t)(c + 1) * BSZH, c + 1, l0, d, n,
                        sAa[(c + 1) & 1], sBa[(c + 1) & 1], tid);
            asm volatile("cp.async.wait_group 1;" ::: "memory");
        } else {
            asm volatile("cp.async.wait_group 0;" ::: "memory");
        }
        __syncthreads();
        const unsigned* Abuf = Abf[c & 1];
        const unsigned* Bbuf = Bbf[c & 1];
#pragma unroll
        for (int ks = 0; ks < 3; ks++) {
            int rowb = wm * 32 + ks * d + grp;
            unsigned a[2][4], b[8][2];
#pragma unroll
            for (int i = 0; i < 2; i++) {
                int rb = rowb + i * 16;
                a[i][0] = Abuf[rb * AP + tig];
                a[i][1] = Abuf[(rb + 8) * AP + tig];
                a[i][2] = Abuf[rb * AP + tig + 4];
                a[i][3] = Abuf[(rb + 8) * AP + tig + 4];
            }
#pragma unroll
            for (int j = 0; j < 8; j++) {
                uint2 bv = ((const uint2*)Bbuf)[(ks * 32 + wn * 8 + j) * 32 + lane];
                b[j][0] = bv.x; b[j][1] = bv.y;
            }
#pragma unroll
            for (int i = 0; i < 2; i++)
#pragma unroll
                for (int j = 0; j < 8; j++) {
                    asm volatile(
                        "mma.sync.aligned.m16n8k16.row.col.f32.f16.f16.f32 "
                        "{%0,%1,%2,%3}, {%4,%5,%6,%7}, {%8,%9}, {%0,%1,%2,%3};"
                        : "+f"(acc[i][j][0]), "+f"(acc[i][j][1]),
                          "+f"(acc[i][j][2]), "+f"(acc[i][j][3])
                        : "r"(a[i][0]), "r"(a[i][1]), "r"(a[i][2]), "r"(a[i][3]),
                          "r"(b[j][0]), "r"(b[j][1]));
                }
        }
        __syncthreads();
    }

    // Epilogue: bias + gelu(c)+c
#pragma unroll
    for (int j = 0; j < 8; j++) {
        int oc0 = wn * 64 + j * 8 + tig * 2;
        float b0 = bias[oc0], b1 = bias[oc0 + 1];
#pragma unroll
        for (int i = 0; i < 2; i++) {
            int posb = l0 + wm * 32 + i * 16 + grp;
            float v[4];
#pragma unroll
            for (int cr = 0; cr < 4; cr++) {
                float cc = acc[i][j][cr] + ((cr & 1) ? b1 : b0);
                v[cr] = 0.5f * cc * (1.f + erff(cc * 0.70710678118654752f)) + cc;
            }
            if (last) {
                g_headsF[((size_t)n * HID + oc0) * LC + posb] = v[0];
                g_headsF[((size_t)n * HID + oc0 + 1) * LC + posb] = v[1];
                g_headsF[((size_t)n * HID + oc0) * LC + posb + 8] = v[2];
                g_headsF[((size_t)n * HID + oc0 + 1) * LC + posb + 8] = v[3];
            } else {
                *(__half2*)(actOut + (size_t)(n * LC + posb) * HID + oc0) =
                    __floats2half2_rn(v[0], v[1]);
                *(__half2*)(actOut + (size_t)(n * LC + posb + 8) * HID + oc0) =
                    __floats2half2_rn(v[2], v[3]);
            }
        }
    }
}

// ---------------------------------------------------------------------------
// Heads, pos-split: grid (2 halves, 256 chunks). Each CTA covers 256 pos
// with a [pb-16, pb+272) halo window per 4-ic group (288 floats/row,
// 16B-aligned, zero-filled outside [0,512)). Writes its profile half and an
// atpm partial sum; finalize_kernel combines + masks.
// ---------------------------------------------------------------------------
__global__ __launch_bounds__(256)
void heads_kernel(const float* __restrict__ w_prof, const float* __restrict__ b_prof,
                  const float* __restrict__ w_atpm, float* __restrict__ out) {
    int ph = blockIdx.x;
    int n = blockIdx.y;
    int pb = ph * 256;
    int tid = threadIdx.x;

    __shared__ float wp[HID * 20];
    __shared__ float wa[HID];
    __shared__ __align__(16) float rows[2][4][288];
    __shared__ float partial[256];

    for (int i = tid; i < HID * 20; i += 256) wp[i] = w_prof[i];
    wa[tid] = w_atpm[tid];

    const float* base = g_headsF + (size_t)n * HID * LC;
    uint32_t rsh = (uint32_t)__cvta_generic_to_shared(&rows[0][0][0]);

    auto stage = [&](int g, int buf) {
#pragma unroll
        for (int r2 = 0; r2 < 2; r2++) {
            int idx = r2 * 256 + tid;       // 0..511, need < 288
            if (idx < 288) {
                int r = idx / 72;
                int pc = idx - r * 72;
                int pos = pb - 16 + pc * 4;
                int ok = (pos >= 0 && pos < LC) ? 16 : 0;
                const float* gs = base + (size_t)(g * 4 + r) * LC + (ok ? pos : 0);
                asm volatile("cp.async.cg.shared.global [%0], [%1], 16, %2;"
                             :: "r"(rsh + (unsigned)(buf * 4 * 288 + r * 288 + pc * 4) * 4u),
                                "l"(__cvta_generic_to_global(gs)), "r"(ok));
            }
        }
        asm volatile("cp.async.commit_group;" ::: "memory");
    };

    float p = 0.f, ap = 0.f;
    stage(0, 0);
    for (int g = 0; g < 64; g++) {
        if (g < 63) {
            stage(g + 1, (g + 1) & 1);
            asm volatile("cp.async.wait_group 1;" ::: "memory");
        } else {
            asm volatile("cp.async.wait_group 0;" ::: "memory");
        }
        __syncthreads();
        const float* rg = &rows[g & 1][0][0];
#pragma unroll
        for (int r = 0; r < 4; r++) {
            int ic = g * 4 + r;
            const float* row = rg + r * 288;
            const float* wpr = &wp[ic * 20];
#pragma unroll
            for (int k = 0; k < 20; k++)
                p = fmaf(row[tid + 7 + k], wpr[k], p);
            ap = fmaf(wa[ic], row[tid + 16], ap);
        }
        __syncthreads();
    }

    out[256 + (size_t)n * LC + pb + tid] = p + b_prof[0];

    partial[tid] = ap;
    __syncthreads();
    for (int s = 128; s > 0; s >>= 1) {
        if (tid < s) partial[tid] += partial[tid + s];
        __syncthreads();
    }
    if (tid == 0) g_atpmP[n * 2 + ph] = partial[0];
}

__global__ void finalize_kernel(const float* __restrict__ b_atpm,
                                const int* __restrict__ npq,
                                float* __restrict__ out) {
    int n = threadIdx.x;
    float atpm = (g_atpmP[n * 2] + g_atpmP[n * 2 + 1]) * (1.f / 512.f) + b_atpm[0];
    int b = n >> 7, p = n & 127;
    int np;
    int q0 = npq[0], q1 = npq[1];
    if (q1 == 0) {
        int q2 = npq[2], q3 = npq[3];
        if (q3 == 0 && q2 >= 0 && q2 < 128 && q0 >= 0 && q0 < 128)
            np = (b == 0) ? q0 : q2;   // little-endian int64 [n0, n1]
        else
            np = (b == 0) ? q0 : q1;
    } else np = (b == 0) ? q0 : q1;
    out[n] = (p < np) ? atpm : 0.f;
}

// ---------------------------------------------------------------------------
extern "C" void kernel_launch(void* const* d_in, const int* in_sizes, int n_in,
                              void* d_out, int out_size) {
    const float* x       = (const float*)d_in[0];
    const float* w_proj  = (const float*)d_in[1];
    const float* tower_w = (const float*)d_in[2];
    const float* tower_b = (const float*)d_in[3];
    const float* w_prof  = (const float*)d_in[4];
    const float* b_prof  = (const float*)d_in[5];
    const float* w_atpm  = (const float*)d_in[6];
    const float* b_atpm  = (const float*)d_in[7];
    const int*   n_peaks = (const int*)d_in[8];
    float* out = (float*)d_out;

    cudaFuncSetAttribute(conv_kernel,
                         cudaFuncAttributeMaxDynamicSharedMemorySize, CONV_SMEM);
    cudaFuncSetAttribute(proj_kernel,
                         cudaFuncAttributeMaxDynamicSharedMemorySize, PROJ_SMEM);

    prep_kernel<<<(DEPTH * 16 * BSZH + 255) / 256, 256>>>(tower_w, w_proj);
    proj_kernel<<<LTOT / 128, 512, PROJ_SMEM>>>(x);
    for (int i = 0; i < DEPTH; i++)
        conv_kernel<<<dim3(LC / 128, NCHUNK), 512, CONV_SMEM>>>(
            i, 2 << i, i & 1, i == DEPTH - 1, tower_b + i * HID);
    heads_kernel<<<dim3(2, NCHUNK), 256>>>(w_prof, b_prof, w_atpm, out);
    finalize_kernel<<<1, 256>>>(b_atpm, n_peaks, out);
}

// round 17
// speedup vs baseline: 1.4354x; 1.0464x over previous
#include <cuda_runtime.h>
#include <cuda_fp16.h>
#include <math.h>
#include <stdint.h>

#define NCHUNK 256
#define LC 512
#define HID 256
#define MD 283
#define DEPTH 7
#define LTOT (NCHUNK * LC)

// ---- conv smem geometry (fp16, 16-ic chunks, 2-buffer) ----
#define AP 36                 // A pitch in 4B words; frag LDS banks (4*grp+tig) all-distinct
#define AROWS 384             // max window 128 + 2*128
#define ASZ (AROWS * AP)      // 13824 words per A buffer
#define BSZH 6144             // words per B buffer (3 ks x 16 ntile-pairs x 32 lane x 4)
#define CONV_SMEM (2 * (ASZ + BSZH) * 4)   // 159744 bytes

// ---- proj smem geometry (tf32 path) ----
#define P2 52
#define A2SZ (128 * P2)
#define BSZ 12288
#define PROJ_SMEM (2 * (A2SZ + BSZ) * 4)

// Activation ping-pong, half, layout [n][pos][ch]
__device__ __half g_act[2][(size_t)LTOT * HID];
// Final conv layer output for heads: fp32 [n][ch][pos]
__device__ float g_headsF[(size_t)NCHUNK * HID * LC];
// Tower weights, m16n8k16 fp16 B-fragments packed as uint4 j-pairs:
// [layer][kc16(16)][ks(3)][ntpair(16)][lane(32)][word(4)]
__device__ unsigned g_wH[DEPTH * 16 * BSZH];
// Proj weights, tf32 fragment layout: [kstep(36)][ntile(32)][lane(32)][reg(2)]
__device__ float g_wpF[36 * 2048];

// ---------------------------------------------------------------------------
// Weight prep
// ---------------------------------------------------------------------------
__global__ void prep_kernel(const float* __restrict__ tower_w,
                            const float* __restrict__ w_proj) {
    int i = blockIdx.x * blockDim.x + threadIdx.x;
    if (i < DEPTH * 16 * BSZH) {
        int local = i % BSZH;
        int blk = i / BSZH;
        int kc16 = blk & 15;
        int layer = blk >> 4;
        int w4 = local & 3;                 // word within uint4
        int r = w4 & 1;
        int ntlow = (w4 >> 1) & 1;
        int lane = (local >> 2) & 31;
        int nt2 = (local >> 7) & 15;
        int ks = local >> 11;               // tap 0..2
        int nt = nt2 * 2 + ntlow;
        int g = lane >> 2, t = lane & 3;
        int ic = kc16 * 16 + 2 * t + 8 * r;
        int oc = nt * 8 + g;
        float w0 = tower_w[((layer * HID + oc) * HID + ic) * 3 + ks];
        float w1 = tower_w[((layer * HID + oc) * HID + ic + 1) * 3 + ks];
        __half2 h2 = __floats2half2_rn(w0, w1);
        g_wH[i] = *(unsigned*)&h2;
    }
    if (i < 36 * 2048) {
        int reg = i & 1;
        int ln = (i >> 1) & 31;
        int nt = (i >> 6) & 31;
        int ks = i >> 11;
        int h = nt * 8 + (ln >> 2);
        int m = ks * 8 + (ln & 3) + 4 * reg;
        float v = (m < MD) ? w_proj[h * MD + m] : 0.f;
        unsigned tv; asm("cvt.rna.tf32.f32 %0, %1;" : "=r"(tv) : "f"(v));
        g_wpF[i] = __uint_as_float(tv);
    }
}

// ---------------------------------------------------------------------------
// Projection via mma.sync tf32; epilogue writes half [n][pos][ch].
// ---------------------------------------------------------------------------
__global__ __launch_bounds__(512, 1)
void proj_kernel(const float* __restrict__ x) {
    extern __shared__ float sm[];
    float* Ab[2] = {sm, sm + A2SZ};
    float* Bb[2] = {sm + 2 * A2SZ, sm + 2 * A2SZ + BSZ};
    uint32_t sbase = (uint32_t)__cvta_generic_to_shared(sm);
    uint32_t sAa[2] = {sbase, sbase + A2SZ * 4};
    uint32_t sBa[2] = {sbase + 2 * A2SZ * 4, sbase + (2 * A2SZ + BSZ) * 4};

    int m0 = blockIdx.x * 128;
    int tid = threadIdx.x;
    int lane = tid & 31;
    int warp = tid >> 5;
    int wm = warp & 3;
    int wn = warp >> 2;
    int tig = lane & 3;
    int grp = lane >> 2;

    float acc[2][8][4];
#pragma unroll
    for (int i = 0; i < 2; i++)
#pragma unroll
        for (int j = 0; j < 8; j++)
#pragma unroll
            for (int c = 0; c < 4; c++) acc[i][j][c] = 0.f;

    auto stage = [&](int c) {
        int kc = c * 48;
#pragma unroll
        for (int r = 0; r < 12; r++) {
            int idx = r * 512 + tid;
            int pos = idx / 48;
            int k = idx - pos * 48;
            int gk = kc + k;
            int ok = (gk < MD) ? 4 : 0;
            const float* gs = x + (size_t)(m0 + pos) * MD + (ok ? gk : 0);
            asm volatile("cp.async.ca.shared.global [%0], [%1], 4, %2;"
                         :: "r"(sAa[c & 1] + (unsigned)(pos * P2 + k) * 4u),
                            "l"(__cvta_generic_to_global(gs)), "r"(ok));
        }
        const float* ws = g_wpF + (size_t)c * BSZ;
#pragma unroll
        for (int r = 0; r < 6; r++) {
            int idx = r * 512 + tid;
            asm volatile("cp.async.cg.shared.global [%0], [%1], 16, 16;"
                         :: "r"(sBa[c & 1] + (unsigned)idx * 16u),
                            "l"(__cvta_generic_to_global(ws + idx * 4)));
        }
        asm volatile("cp.async.commit_group;" ::: "memory");
    };

    stage(0);
    for (int c = 0; c < 6; c++) {
        if (c < 5) {
            stage(c + 1);
            asm volatile("cp.async.wait_group 1;" ::: "memory");
        } else {
            asm volatile("cp.async.wait_group 0;" ::: "memory");
        }
        __syncthreads();
        const float* Abuf = Ab[c & 1];
        const float* Bbuf = Bb[c & 1];
#pragma unroll
        for (int ks = 0; ks < 6; ks++) {
            unsigned a[2][4], b[8][2];
#pragma unroll
            for (int i = 0; i < 2; i++) {
                const float* ar = Abuf + (wm * 32 + i * 16 + grp) * P2 + ks * 8 + tig;
                a[i][0] = __float_as_uint(ar[0]);
                a[i][1] = __float_as_uint(ar[8 * P2]);
                a[i][2] = __float_as_uint(ar[4]);
                a[i][3] = __float_as_uint(ar[8 * P2 + 4]);
            }
#pragma unroll
            for (int j = 0; j < 8; j++) {
                uint2 bv = ((const uint2*)Bbuf)[(ks * 32 + wn * 8 + j) * 32 + lane];
                b[j][0] = bv.x; b[j][1] = bv.y;
            }
#pragma unroll
            for (int i = 0; i < 2; i++)
#pragma unroll
                for (int j = 0; j < 8; j++) {
                    asm volatile(
                        "mma.sync.aligned.m16n8k8.row.col.f32.tf32.tf32.f32 "
                        "{%0,%1,%2,%3}, {%4,%5,%6,%7}, {%8,%9}, {%0,%1,%2,%3};"
                        : "+f"(acc[i][j][0]), "+f"(acc[i][j][1]),
                          "+f"(acc[i][j][2]), "+f"(acc[i][j][3])
                        : "r"(a[i][0]), "r"(a[i][1]), "r"(a[i][2]), "r"(a[i][3]),
                          "r"(b[j][0]), "r"(b[j][1]));
                }
        }
        __syncthreads();
    }

    int n = m0 >> 9;
    __half* outp = g_act[0];
#pragma unroll
    for (int j = 0; j < 8; j++) {
        int h0 = wn * 64 + j * 8 + tig * 2;
#pragma unroll
        for (int i = 0; i < 2; i++) {
            int posb = (m0 & 511) + wm * 32 + i * 16 + grp;
            __half2 lo = __floats2half2_rn(acc[i][j][0], acc[i][j][1]);
            __half2 hi = __floats2half2_rn(acc[i][j][2], acc[i][j][3]);
            *(__half2*)(outp + (size_t)(n * LC + posb) * HID + h0) = lo;
            *(__half2*)(outp + (size_t)(n * LC + posb + 8) * HID + h0) = hi;
        }
    }
}

// ---------------------------------------------------------------------------
// Stage one conv K-chunk: A = window [l0-d, l0+128+d) x 16 ic (half, 32B/row,
// 2 x 16B cp.async), tap-shared. B = packed uint4 fragments.
// ---------------------------------------------------------------------------
__device__ __forceinline__ void stage_chunk(const __half* __restrict__ actIn,
                                            const unsigned* __restrict__ wsrc,
                                            int kc16, int l0, int d, int n,
                                            uint32_t sA, uint32_t sB, int tid) {
    int ic0 = kc16 * 16;
    int rows = 128 + 2 * d;
    int total = rows * 2;                // 16B pieces
#pragma unroll
    for (int r = 0; r < 2; r++) {
        int idx = r * 512 + tid;
        if (idx < total) {
            int row = idx >> 1;
            int pc = idx & 1;
            int pos = l0 - d + row;
            int ok = ((unsigned)pos < (unsigned)LC) ? 16 : 0;
            const __half* gs = actIn + (size_t)(n * LC + (ok ? pos : 0)) * HID
                               + ic0 + pc * 8;
            asm volatile("cp.async.cg.shared.global [%0], [%1], 16, %2;"
                         :: "r"(sA + (unsigned)(row * AP + pc * 4) * 4u),
                            "l"(__cvta_generic_to_global(gs)), "r"(ok));
        }
    }
#pragma unroll
    for (int r = 0; r < 3; r++) {
        int idx = r * 512 + tid;
        asm volatile("cp.async.cg.shared.global [%0], [%1], 16, 16;"
                     :: "r"(sB + (unsigned)idx * 16u),
                        "l"(__cvta_generic_to_global(wsrc + idx * 4)));
    }
    asm volatile("cp.async.commit_group;" ::: "memory");
}

// ---------------------------------------------------------------------------
// Dilated conv layer via mma.sync m16n8k16 fp16.
// CTA 128 pos x 256 oc, 512 threads; K = 768 in 16 chunks, double-buffered.
// B fragment loads are LDS.128 j-pairs.
// ---------------------------------------------------------------------------
__global__ __launch_bounds__(512, 1)
void conv_kernel(int layer, int d, int src, int last,
                 const float* __restrict__ bias) {
    extern __shared__ unsigned smu[];
    const unsigned* Abf[2] = {smu, smu + ASZ};
    const unsigned* Bbf[2] = {smu + 2 * ASZ, smu + 2 * ASZ + BSZH};
    uint32_t sbase = (uint32_t)__cvta_generic_to_shared(smu);
    uint32_t sAa[2] = {sbase, sbase + ASZ * 4};
    uint32_t sBa[2] = {sbase + 2 * ASZ * 4, sbase + (2 * ASZ + BSZH) * 4};

    const __half* actIn = g_act[src];
    __half* actOut = g_act[src ^ 1];
    int l0 = blockIdx.x * 128;
    int n = blockIdx.y;

    int tid = threadIdx.x;
    int lane = tid & 31;
    int warp = tid >> 5;
    int wm = warp & 3;
    int wn = warp >> 2;
    int tig = lane & 3;
    int grp = lane >> 2;

    float acc[2][8][4];
#pragma unroll
    for (int i = 0; i < 2; i++)
#pragma unroll
        for (int j = 0; j < 8; j++)
#pragma unroll
            for (int c = 0; c < 4; c++) acc[i][j][c] = 0.f;

    const unsigned* wbase = g_wH + (size_t)layer * 16 * BSZH;
    stage_chunk(actIn, wbase, 0, l0, d, n, sAa[0], sBa[0], tid);

    for (int c = 0; c < 16; c++) {
        if (c < 15) {
            stage_chunk(actIn, wbase + (size_t)(c + 1) * BSZH, c + 1, l0, d, n,
                        sAa[(c + 1) & 1], sBa[(c + 1) & 1], tid);
            asm volatile("cp.async.wait_group 1;" ::: "memory");
        } else {
            asm volatile("cp.async.wait_group 0;" ::: "memory");
        }
        __syncthreads();
        const unsigned* Abuf = Abf[c & 1];
        const unsigned* Bbuf = Bbf[c & 1];
#pragma unroll
        for (int ks = 0; ks < 3; ks++) {
            int rowb = wm * 32 + ks * d + grp;
            unsigned a[2][4], b[8][2];
#pragma unroll
            for (int i = 0; i < 2; i++) {
                int rb = rowb + i * 16;
                a[i][0] = Abuf[rb * AP + tig];
                a[i][1] = Abuf[(rb + 8) * AP + tig];
                a[i][2] = Abuf[rb * AP + tig + 4];
                a[i][3] = Abuf[(rb + 8) * AP + tig + 4];
            }
#pragma unroll
            for (int j2 = 0; j2 < 4; j2++) {
                uint4 bv = ((const uint4*)Bbuf)[(ks * 16 + wn * 4 + j2) * 32 + lane];
                b[2 * j2][0] = bv.x; b[2 * j2][1] = bv.y;
                b[2 * j2 + 1][0] = bv.z; b[2 * j2 + 1][1] = bv.w;
            }
#pragma unroll
            for (int i = 0; i < 2; i++)
#pragma unroll
                for (int j = 0; j < 8; j++) {
                    asm volatile(
                        "mma.sync.aligned.m16n8k16.row.col.f32.f16.f16.f32 "
                        "{%0,%1,%2,%3}, {%4,%5,%6,%7}, {%8,%9}, {%0,%1,%2,%3};"
                        : "+f"(acc[i][j][0]), "+f"(acc[i][j][1]),
                          "+f"(acc[i][j][2]), "+f"(acc[i][j][3])
                        : "r"(a[i][0]), "r"(a[i][1]), "r"(a[i][2]), "r"(a[i][3]),
                          "r"(b[j][0]), "r"(b[j][1]));
                }
        }
        __syncthreads();
    }

    // Epilogue: bias + gelu(c)+c
#pragma unroll
    for (int j = 0; j < 8; j++) {
        int oc0 = wn * 64 + j * 8 + tig * 2;
        float b0 = bias[oc0], b1 = bias[oc0 + 1];
#pragma unroll
        for (int i = 0; i < 2; i++) {
            int posb = l0 + wm * 32 + i * 16 + grp;
            float v[4];
#pragma unroll
            for (int cr = 0; cr < 4; cr++) {
                float cc = acc[i][j][cr] + ((cr & 1) ? b1 : b0);
                v[cr] = 0.5f * cc * (1.f + erff(cc * 0.70710678118654752f)) + cc;
            }
            if (last) {
                g_headsF[((size_t)n * HID + oc0) * LC + posb] = v[0];
                g_headsF[((size_t)n * HID + oc0 + 1) * LC + posb] = v[1];
                g_headsF[((size_t)n * HID + oc0) * LC + posb + 8] = v[2];
                g_headsF[((size_t)n * HID + oc0 + 1) * LC + posb + 8] = v[3];
            } else {
                *(__half2*)(actOut + (size_t)(n * LC + posb) * HID + oc0) =
                    __floats2half2_rn(v[0], v[1]);
                *(__half2*)(actOut + (size_t)(n * LC + posb + 8) * HID + oc0) =
                    __floats2half2_rn(v[2], v[3]);
            }
        }
    }
}

// ---------------------------------------------------------------------------
// Heads: profile conv (K=20, pad 9/10) + mean-pool + atpm + mask (R13 form).
// ---------------------------------------------------------------------------
__global__ __launch_bounds__(256)
void heads_kernel(const float* __restrict__ w_prof, const float* __restrict__ b_prof,
                  const float* __restrict__ w_atpm, const float* __restrict__ b_atpm,
                  const int* __restrict__ npq, float* __restrict__ out) {
    const float* in = g_headsF;
    int n = blockIdx.x;
    int tid = threadIdx.x;

    __shared__ float wp[HID * 20];
    __shared__ float wa[HID];
    __shared__ __align__(16) float rows[2][4][LC];
    __shared__ float partial[256];

    for (int i = tid; i < HID * 20; i += 256) wp[i] = w_prof[i];
    wa[tid] = w_atpm[tid];

    const float* base = in + (size_t)n * HID * LC;
    uint32_t rsh = (uint32_t)__cvta_generic_to_shared(&rows[0][0][0]);

    auto stage = [&](int g, int buf) {
#pragma unroll
        for (int r2 = 0; r2 < 2; r2++) {
            int idx = r2 * 256 + tid;
            int r = idx >> 7;
            int pc = idx & 127;
            const float* gs = base + (size_t)(g * 4 + r) * LC + pc * 4;
            asm volatile("cp.async.cg.shared.global [%0], [%1], 16, 16;"
                         :: "r"(rsh + (unsigned)(buf * 4 * LC + r * LC + pc * 4) * 4u),
                            "l"(__cvta_generic_to_global(gs)));
        }
        asm volatile("cp.async.commit_group;" ::: "memory");
    };

    float p0 = 0.f, p1 = 0.f, ap = 0.f;
    stage(0, 0);
    for (int g = 0; g < 64; g++) {
        if (g < 63) {
            stage(g + 1, (g + 1) & 1);
            asm volatile("cp.async.wait_group 1;" ::: "memory");
        } else {
            asm volatile("cp.async.wait_group 0;" ::: "memory");
        }
        __syncthreads();
        const float* rg = &rows[g & 1][0][0];
#pragma unroll
        for (int r = 0; r < 4; r++) {
            int ic = g * 4 + r;
            const float* row = rg + r * LC;
            const float* wpr = &wp[ic * 20];
            float wv = wa[ic];
#pragma unroll
            for (int k = 0; k < 20; k++) {
                float w = wpr[k];
                int pos = tid + k - 9;
                if (pos >= 0 && pos < LC) p0 = fmaf(row[pos], w, p0);
                int pos2 = tid + 256 + k - 9;
                if (pos2 < LC) p1 = fmaf(row[pos2], w, p1);
            }
            ap = fmaf(wv, row[tid] + row[tid + 256], ap);
        }
        __syncthreads();
    }

    float bp = b_prof[0];
    out[256 + (size_t)n * LC + tid] = p0 + bp;
    out[256 + (size_t)n * LC + tid + 256] = p1 + bp;

    partial[tid] = ap;
    __syncthreads();
    for (int s = 128; s > 0; s >>= 1) {
        if (tid < s) partial[tid] += partial[tid + s];
        __syncthreads();
    }
    if (tid == 0) {
        float atpm = partial[0] * (1.f / 512.f) + b_atpm[0];
        int b = n >> 7, p = n & 127;
        int np;
        int q0 = npq[0], q1 = npq[1];
        if (q1 == 0) {
            int q2 = npq[2], q3 = npq[3];
            if (q3 == 0 && q2 >= 0 && q2 < 128 && q0 >= 0 && q0 < 128)
                np = (b == 0) ? q0 : q2;   // little-endian int64 [n0, n1]
            else
                np = (b == 0) ? q0 : q1;
        } else np = (b == 0) ? q0 : q1;
        out[n] = (p < np) ? atpm : 0.f;
    }
}

// ---------------------------------------------------------------------------
extern "C" void kernel_launch(void* const* d_in, const int* in_sizes, int n_in,
                              void* d_out, int out_size) {
    const float* x       = (const float*)d_in[0];
    const float* w_proj  = (const float*)d_in[1];
    const float* tower_w = (const float*)d_in[2];
    const float* tower_b = (const float*)d_in[3];
    const float* w_prof  = (const float*)d_in[4];
    const float* b_prof  = (const float*)d_in[5];
    const float* w_atpm  = (const float*)d_in[6];
    const float* b_atpm  = (const float*)d_in[7];
    const int*   n_peaks = (const int*)d_in[8];
    float* out = (float*)d_out;

    cudaFuncSetAttribute(conv_kernel,
                         cudaFuncAttributeMaxDynamicSharedMemorySize, CONV_SMEM);
    cudaFuncSetAttribute(proj_kernel,
                         cudaFuncAttributeMaxDynamicSharedMemorySize, PROJ_SMEM);

    prep_kernel<<<(DEPTH * 16 * BSZH + 255) / 256, 256>>>(tower_w, w_proj);
    proj_kernel<<<LTOT / 128, 512, PROJ_SMEM>>>(x);
    for (int i = 0; i < DEPTH; i++)
        conv_kernel<<<dim3(LC / 128, NCHUNK), 512, CONV_SMEM>>>(
            i, 2 << i, i & 1, i == DEPTH - 1, tower_b + i * HID);
    heads_kernel<<<NCHUNK, 256>>>(w_prof, b_prof, w_atpm, b_atpm, n_peaks, out);
}